// round 14
// baseline (speedup 1.0000x reference)
#include <cuda_runtime.h>

// EnergyModel: energy[t] = sum_q qa[q] * sum_f w[f]*(desc[t,q,f]-qf[t,q,f])^2
// with range masking on T[:,4:7]. HBM-bound streaming reduction.
//
// R14: R12's single-kernel structure (in-producer last-CTA-per-row fold =
// zero finalize exposure) with the load batch pinned in SASS via inline-PTX
// volatile ld.global.v4.f32. R10-R13 showed ptxas sinks plain LDGs to first
// use (regs 46->39, MLP 6->~2, 5.9->5.06 TB/s); volatile asm loads are
// opaque fixed-order statements ptxas cannot sink or interleave.

#define NQ 128
#define FDIM 576                    // 64*1 + 64*3 + 64*5
#define NGRP 192
#define SPLIT 8
#define QPC (NQ / SPLIT)            // 16 queries per chunk
#define THREADS 256
#define F4_PER_ROW (FDIM / 4)       // 144
#define F4_TOTAL (NQ * F4_PER_ROW)  // 18432 float4 per t per tensor
#define CHUNK_F4 (QPC * F4_PER_ROW) // 2304 float4 per chunk per tensor
#define NT_MAX 1024
#define NBATCH 3
#define UB 3                        // float4-pairs batched per phase (MLP=6)

__device__ float g_partial[NT_MAX * SPLIT];
__device__ int   g_count[NT_MAX];    // zero-init; folding CTA resets to 0

// Volatile vector load: ptxas may not sink, split, or reorder these.
__device__ __forceinline__ float4 ldg128_pinned(const float4* p)
{
    float4 v;
    asm volatile("ld.global.v4.f32 {%0, %1, %2, %3}, [%4];"
                 : "=f"(v.x), "=f"(v.y), "=f"(v.z), "=f"(v.w)
                 : "l"(p));
    return v;
}

__global__ void __launch_bounds__(THREADS)
energy_kernel(const float* __restrict__ T,
              const float4* __restrict__ desc,
              const float4* __restrict__ qf,
              const float* __restrict__ qa,
              const float* __restrict__ logit,
              const float* __restrict__ ranges,
              float* __restrict__ out)
{
    const int bx  = blockIdx.x;
    const int t   = bx >> 3;             // SPLIT == 8
    const int c   = bx & (SPLIT - 1);
    const int tid = threadIdx.x;

    // Range mask: uniform predicate; dead CTAs retire without touching payload.
    {
        const float x0 = T[t * 7 + 4];
        const float x1 = T[t * 7 + 5];
        const float x2 = T[t * 7 + 6];
        const bool ok = (ranges[1] >= x0) && (x0 >= ranges[0]) &&
                        (ranges[3] >= x1) && (x1 >= ranges[2]) &&
                        (ranges[5] >= x2) && (x2 >= ranges[4]);
        if (!ok) {
            if (c == 0 && tid == 0) out[t] = 100000.0f;
            return;
        }
    }

    __shared__ float s_g[NGRP];
    __shared__ float s_w[FDIM];
    __shared__ float s_qa[QPC];
    __shared__ float s_red[THREADS / 32];

    // Weight setup: 192 softplus -> expand to 576 per-feature weights (LDS only).
    const float scale = 2.0f / (0.6931471805599453f * (float)NGRP);
    if (tid < NGRP) {
        const float x = logit[tid];
        s_g[tid] = (fmaxf(x, 0.0f) + log1pf(expf(-fabsf(x)))) * scale;
    }
    if (tid < QPC) s_qa[tid] = qa[c * QPC + tid];
    __syncthreads();
    for (int f = tid; f < FDIM; f += THREADS) {
        int g;
        if (f < 64)        g = f;                    // l=0, d=1
        else if (f < 256)  g = 64 + (f - 64) / 3;    // l=1, d=3
        else               g = 128 + (f - 256) / 5;  // l=2, d=5
        s_w[f] = s_g[g];
    }
    __syncthreads();

    const float4* db = desc + (size_t)t * F4_TOTAL + (size_t)c * CHUNK_F4;
    const float4* qb = qf   + (size_t)t * F4_TOTAL + (size_t)c * CHUNK_F4;
    const float4* s_w4 = (const float4*)s_w;

    float acc = 0.0f;
    #pragma unroll
    for (int b = 0; b < NBATCH; b++) {
        float4 dv[UB], ev[UB];
        // Phase 1: 6 pinned LDG.128 issued back-to-back (MLP_p1 = 6).
        #pragma unroll
        for (int u = 0; u < UB; u++) {
            const int j = tid + (b * UB + u) * THREADS;
            dv[u] = ldg128_pinned(db + j);
            ev[u] = ldg128_pinned(qb + j);
        }
        // Phase 2: consume.
        #pragma unroll
        for (int u = 0; u < UB; u++) {
            const int j  = tid + (b * UB + u) * THREADS;
            const int q  = j / F4_PER_ROW;
            const int f4 = j - q * F4_PER_ROW;
            const float4 w = s_w4[f4];
            const float dx = dv[u].x - ev[u].x;
            const float dy = dv[u].y - ev[u].y;
            const float dz = dv[u].z - ev[u].z;
            const float dw = dv[u].w - ev[u].w;
            float s = w.x * dx * dx;
            s = fmaf(w.y, dy * dy, s);
            s = fmaf(w.z, dz * dz, s);
            s = fmaf(w.w, dw * dw, s);
            acc = fmaf(s_qa[q], s, acc);
        }
    }

    // Block reduction (8 warps).
    #pragma unroll
    for (int o = 16; o > 0; o >>= 1)
        acc += __shfl_down_sync(0xffffffffu, acc, o);
    if ((tid & 31) == 0) s_red[tid >> 5] = acc;
    __syncthreads();

    if (tid == 0) {
        float v = 0.0f;
        #pragma unroll
        for (int w = 0; w < THREADS / 32; w++) v += s_red[w];
        g_partial[bx] = v;                 // publish partial...
        __threadfence();                   // ...release...
        const int prev = atomicAdd(&g_count[t], 1);
        if (prev == SPLIT - 1) {           // 8th arriver folds this row
            __threadfence();               // acquire peer partials
            const float4 a = __ldcg((const float4*)&g_partial[t * SPLIT]);
            const float4 b = __ldcg((const float4*)&g_partial[t * SPLIT + 4]);
            out[t] = ((a.x + a.y) + (a.z + a.w)) +
                     ((b.x + b.y) + (b.z + b.w));
            g_count[t] = 0;                // reset for next graph replay
        }
    }
}

extern "C" void kernel_launch(void* const* d_in, const int* in_sizes, int n_in,
                              void* d_out, int out_size)
{
    const float*  T      = (const float*)d_in[0];
    const float4* desc   = (const float4*)d_in[1];
    const float4* qf     = (const float4*)d_in[2];
    const float*  qa     = (const float*)d_in[3];
    const float*  logit  = (const float*)d_in[4];
    const float*  ranges = (const float*)d_in[5];
    float* out = (float*)d_out;

    const int nt = in_sizes[0] / 7;   // 1024

    energy_kernel<<<nt * SPLIT, THREADS>>>(T, desc, qf, qa, logit, ranges, out);
}

// round 15
// speedup vs baseline: 1.0585x; 1.0585x over previous
#include <cuda_runtime.h>

// EnergyModel: energy[t] = sum_q qa[q] * sum_f w[f]*(desc[t,q,f]-qf[t,q,f])^2
// with range masking on T[:,4:7]. HBM-bound streaming reduction.
//
// R15: champion R8 structure verbatim (two kernels: 3x3-batched streaming
// partial + PDL/gridsync finalize = best measured 35.3us; R12-R14 proved
// in-producer folds tax CTA retirement worse than the 2.8us exposure).
// Single change: __ldcs evict-first policy on the read-once 604MB payload
// stream — same LDG.E.128 register pattern, no codegen risk, less L2 thrash.

#define NQ 128
#define FDIM 576                    // 64*1 + 64*3 + 64*5
#define NGRP 192
#define SPLIT 8
#define QPC (NQ / SPLIT)            // 16 queries per chunk
#define THREADS 256
#define F4_PER_ROW (FDIM / 4)       // 144
#define F4_TOTAL (NQ * F4_PER_ROW)  // 18432 float4 per t per tensor
#define CHUNK_F4 (QPC * F4_PER_ROW) // 2304 float4 per chunk per tensor
#define NT_MAX 1024
#define NBATCH 3
#define UB 3                        // float4-pairs batched per phase (MLP=6)

__device__ float g_partial[NT_MAX * SPLIT];

__global__ void __launch_bounds__(THREADS)
partial_kernel(const float* __restrict__ T,
               const float4* __restrict__ desc,
               const float4* __restrict__ qf,
               const float* __restrict__ qa,
               const float* __restrict__ logit,
               const float* __restrict__ ranges)
{
    // Let the finalize kernel launch as soon as the whole grid has started.
    cudaTriggerProgrammaticLaunchCompletion();

    const int bx  = blockIdx.x;
    const int t   = bx >> 3;             // SPLIT == 8
    const int c   = bx & (SPLIT - 1);
    const int tid = threadIdx.x;

    // Range mask: uniform predicate; dead CTAs retire without touching payload.
    {
        const float x0 = T[t * 7 + 4];
        const float x1 = T[t * 7 + 5];
        const float x2 = T[t * 7 + 6];
        const bool ok = (ranges[1] >= x0) && (x0 >= ranges[0]) &&
                        (ranges[3] >= x1) && (x1 >= ranges[2]) &&
                        (ranges[5] >= x2) && (x2 >= ranges[4]);
        if (!ok) return;
    }

    __shared__ float s_g[NGRP];
    __shared__ float s_w[FDIM];
    __shared__ float s_qa[QPC];
    __shared__ float s_red[THREADS / 32];

    // Weight setup: 192 softplus -> expand to 576 per-feature weights (LDS only).
    const float scale = 2.0f / (0.6931471805599453f * (float)NGRP);
    if (tid < NGRP) {
        const float x = logit[tid];
        s_g[tid] = (fmaxf(x, 0.0f) + log1pf(expf(-fabsf(x)))) * scale;
    }
    if (tid < QPC) s_qa[tid] = qa[c * QPC + tid];
    __syncthreads();
    for (int f = tid; f < FDIM; f += THREADS) {
        int g;
        if (f < 64)        g = f;                    // l=0, d=1
        else if (f < 256)  g = 64 + (f - 64) / 3;    // l=1, d=3
        else               g = 128 + (f - 256) / 5;  // l=2, d=5
        s_w[f] = s_g[g];
    }
    __syncthreads();

    const float4* db = desc + (size_t)t * F4_TOTAL + (size_t)c * CHUNK_F4;
    const float4* qb = qf   + (size_t)t * F4_TOTAL + (size_t)c * CHUNK_F4;
    const float4* s_w4 = (const float4*)s_w;

    float acc = 0.0f;
    #pragma unroll
    for (int b = 0; b < NBATCH; b++) {
        float4 dv[UB], ev[UB];
        // Phase 1: issue all 6 independent streaming loads (MLP_p1 = 6).
        #pragma unroll
        for (int u = 0; u < UB; u++) {
            const int j = tid + (b * UB + u) * THREADS;
            dv[u] = __ldcs(db + j);      // read-once: evict-first policy
            ev[u] = __ldcs(qb + j);
        }
        // Phase 2: consume.
        #pragma unroll
        for (int u = 0; u < UB; u++) {
            const int j  = tid + (b * UB + u) * THREADS;
            const int q  = j / F4_PER_ROW;
            const int f4 = j - q * F4_PER_ROW;
            const float4 w = s_w4[f4];
            const float dx = dv[u].x - ev[u].x;
            const float dy = dv[u].y - ev[u].y;
            const float dz = dv[u].z - ev[u].z;
            const float dw = dv[u].w - ev[u].w;
            float s = w.x * dx * dx;
            s = fmaf(w.y, dy * dy, s);
            s = fmaf(w.z, dz * dz, s);
            s = fmaf(w.w, dw * dw, s);
            acc = fmaf(s_qa[q], s, acc);
        }
    }

    // Block reduction (8 warps).
    #pragma unroll
    for (int o = 16; o > 0; o >>= 1)
        acc += __shfl_down_sync(0xffffffffu, acc, o);
    if ((tid & 31) == 0) s_red[tid >> 5] = acc;
    __syncthreads();
    if (tid == 0) {
        float v = 0.0f;
        #pragma unroll
        for (int w = 0; w < THREADS / 32; w++) v += s_red[w];
        g_partial[bx] = v;
    }
}

__global__ void __launch_bounds__(128)
finalize_kernel(const float* __restrict__ T,
                const float* __restrict__ ranges,
                float* __restrict__ out,
                int nt)
{
    const int t = blockIdx.x * blockDim.x + threadIdx.x;

    // ---- Prologue: everything independent of g_partial (overlaps primary).
    bool ok = false;
    if (t < nt) {
        const float x0 = T[t * 7 + 4];
        const float x1 = T[t * 7 + 5];
        const float x2 = T[t * 7 + 6];
        ok = (ranges[1] >= x0) && (x0 >= ranges[0]) &&
             (ranges[3] >= x1) && (x1 >= ranges[2]) &&
             (ranges[5] >= x2) && (x2 >= ranges[4]);
        if (!ok) out[t] = 100000.0f;     // masked rows: no dependency
    }
    if (!ok) return;                      // exit before the dependency sync

    // ---- Wait for the primary grid's writes to become visible.
    cudaGridDependencySynchronize();

    // 8 contiguous partials = 2 x float4 (fixed-order fold: deterministic).
    const float4* gp = (const float4*)&g_partial[t * SPLIT];
    const float4 a = gp[0];
    const float4 b = gp[1];
    out[t] = ((a.x + a.y) + (a.z + a.w)) + ((b.x + b.y) + (b.z + b.w));
}

extern "C" void kernel_launch(void* const* d_in, const int* in_sizes, int n_in,
                              void* d_out, int out_size)
{
    const float*  T      = (const float*)d_in[0];
    const float4* desc   = (const float4*)d_in[1];
    const float4* qf     = (const float4*)d_in[2];
    const float*  qa     = (const float*)d_in[3];
    const float*  logit  = (const float*)d_in[4];
    const float*  ranges = (const float*)d_in[5];
    float* out = (float*)d_out;

    const int nt = in_sizes[0] / 7;   // 1024

    partial_kernel<<<nt * SPLIT, THREADS>>>(T, desc, qf, qa, logit, ranges);

    // Finalize with Programmatic Stream Serialization: launches as soon as
    // all primary CTAs have triggered, overlapping its prologue with the
    // primary's tail.
    cudaLaunchConfig_t cfg = {};
    cfg.gridDim  = dim3((nt + 127) / 128);
    cfg.blockDim = dim3(128);
    cfg.dynamicSmemBytes = 0;
    cfg.stream = 0;
    cudaLaunchAttribute attrs[1];
    attrs[0].id = cudaLaunchAttributeProgrammaticStreamSerialization;
    attrs[0].val.programmaticStreamSerializationAllowed = 1;
    cfg.attrs = attrs;
    cfg.numAttrs = 1;
    cudaLaunchKernelEx(&cfg, finalize_kernel, T, ranges, out, nt);
}